// round 2
// baseline (speedup 1.0000x reference)
#include <cuda_runtime.h>

// Problem constants
#define T_STEPS 2048
#define BATCH   256
#define IN_DIM  64
#define HID     256

// Recurrent kernel tiling: 8 row-tiles (32 batch rows) x 16 j-tiles (16 hidden cols) = 128 CTAs
#define REC_CTAS 128
#define ROWS 32
#define JT   16
#define HPITCH 260   // 256 + 4 pad (keeps 16B alignment, reduces bank conflicts)
#define XPITCH 68    // 64 + 4 pad

// Dynamic smem layout (floats):
//   w_s  [3*JT][HPITCH]  = 48*260 = 12480
//   wx_s [3*JT][XPITCH]  = 48*68  = 3264
//   h_s  [ROWS][HPITCH]  = 32*260 = 8320
//   x_s  [ROWS][XPITCH]  = 32*68  = 2176
#define SMEM_REC_FLOATS (48*HPITCH + 48*XPITCH + ROWS*HPITCH + ROWS*XPITCH)
#define SMEM_REC_BYTES  (SMEM_REC_FLOATS * 4)

// Device scratch (sanctioned: __device__ globals, no allocation)
__device__ float g_hs[(size_t)T_STEPS * BATCH * HID];   // h trajectory, [T][B][H]
__device__ float g_h[2][BATCH * HID];                   // double-buffered state
__device__ unsigned int g_bar_count;
__device__ volatile unsigned int g_bar_gen;

// ---- packed fp32x2 FMA helpers ----
__device__ __forceinline__ void fma2(unsigned long long& acc, unsigned long long a, unsigned long long b) {
    asm("fma.rn.f32x2 %0, %1, %2, %0;" : "+l"(acc) : "l"(a), "l"(b));
}
__device__ __forceinline__ float redpair(unsigned long long v) {
    float lo = __uint_as_float((unsigned int)(v & 0xffffffffULL));
    float hi = __uint_as_float((unsigned int)(v >> 32));
    return lo + hi;
}

// ---- grid-wide barrier (all CTAs co-resident by construction) ----
__device__ __forceinline__ void grid_barrier() {
    __threadfence();       // make this thread's global writes visible at GPU scope
    __syncthreads();       // all CTA threads' writes fenced before arrival
    if (threadIdx.x == 0) {
        unsigned int gen = g_bar_gen;
        unsigned int n = atomicAdd(&g_bar_count, 1u);
        if (n == gridDim.x - 1) {
            g_bar_count = 0;
            __threadfence();
            g_bar_gen = gen + 1;
        } else {
            while (g_bar_gen == gen) { }
        }
    }
    __syncthreads();
}

// =====================================================================
// Persistent recurrent kernel: h0 projection + 2048 GRU steps
// =====================================================================
__global__ void __launch_bounds__(256, 1) k_rec(
    const float* __restrict__ input,   // [T][B][I]
    const float* __restrict__ hidden,  // [1][B][3]
    const float* __restrict__ W_dec,   // [H][3]
    const float* __restrict__ b_dec,   // [H]
    const float* __restrict__ W_ih,    // [3H][I]
    const float* __restrict__ W_hh,    // [3H][H]
    const float* __restrict__ b_ih,    // [3H]
    const float* __restrict__ b_hh)    // [3H]
{
    extern __shared__ float sm[];
    float* w_s  = sm;                         // [48][HPITCH]
    float* wx_s = w_s  + 48 * HPITCH;         // [48][XPITCH]
    float* h_s  = wx_s + 48 * XPITCH;         // [ROWS][HPITCH]
    float* x_s  = h_s  + ROWS * HPITCH;       // [ROWS][XPITCH]

    const int tid = threadIdx.x;
    const int tx = tid & 15;          // j within tile
    const int ty = tid >> 4;          // row-pair index (0..15)
    const int jbase = (blockIdx.x & 15) * JT;
    const int rbase = (blockIdx.x >> 4) * ROWS;
    const int jg = jbase + tx;        // global hidden column this thread owns

    // --- load W_hh slices for gates r,z,n at columns [jbase, jbase+16) ---
    for (int i = tid; i < 48 * HID; i += 256) {
        int rr = i >> 8;              // 0..47 : gate*16 + j
        int k  = i & 255;
        int g  = rr >> 4;
        int j  = rr & 15;
        w_s[rr * HPITCH + k] = W_hh[((size_t)(g * HID + jbase + j)) * HID + k];
    }
    // --- load W_ih slices ---
    for (int i = tid; i < 48 * IN_DIM; i += 256) {
        int rr = i >> 6;
        int k  = i & 63;
        int g  = rr >> 4;
        int j  = rr & 15;
        wx_s[rr * XPITCH + k] = W_ih[((size_t)(g * HID + jbase + j)) * IN_DIM + k];
    }

    // per-thread biases for column jg
    const float bsum_r = b_ih[jg]           + b_hh[jg];
    const float bsum_z = b_ih[HID + jg]     + b_hh[HID + jg];
    const float bx_n   = b_ih[2 * HID + jg];
    const float bh_n   = b_hh[2 * HID + jg];

    // --- h0 = hidden @ W_dec^T + b_dec, split across all CTAs ---
    {
        int base = blockIdx.x * (BATCH * HID / REC_CTAS);  // 512 per CTA
        for (int u = tid; u < BATCH * HID / REC_CTAS; u += 256) {
            int idx = base + u;
            int b = idx >> 8;
            int j = idx & 255;
            float v = b_dec[j]
                    + hidden[b * 3 + 0] * W_dec[j * 3 + 0]
                    + hidden[b * 3 + 1] * W_dec[j * 3 + 1]
                    + hidden[b * 3 + 2] * W_dec[j * 3 + 2];
            g_h[0][idx] = v;
        }
    }
    grid_barrier();

    // ---------------- time-step loop ----------------
    for (int s = 0; s < T_STEPS; s++) {
        const float* hcur = g_h[s & 1];
        float*       hnxt = g_h[(s & 1) ^ 1];

        // stage h tile [ROWS][HID] (bypass L1: stale across steps)
        {
            const float4* hsrc = (const float4*)(hcur + (size_t)rbase * HID);
            for (int i = tid; i < ROWS * HID / 4; i += 256) {
                float4 v = __ldcg(hsrc + i);
                int row = i >> 6, c = i & 63;
                *(float4*)(h_s + row * HPITCH + c * 4) = v;
            }
        }
        // stage x tile [ROWS][IN_DIM]  (xs[0] = 0, xs[s] = input[s-1])
        if (s == 0) {
            float4 z4 = make_float4(0.f, 0.f, 0.f, 0.f);
            for (int i = tid; i < ROWS * IN_DIM / 4; i += 256) {
                int row = i >> 4, c = i & 15;
                *(float4*)(x_s + row * XPITCH + c * 4) = z4;
            }
        } else {
            const float4* xsrc = (const float4*)(input + ((size_t)(s - 1) * BATCH + rbase) * IN_DIM);
            for (int i = tid; i < ROWS * IN_DIM / 4; i += 256) {
                float4 v = xsrc[i];
                int row = i >> 4, c = i & 15;
                *(float4*)(x_s + row * XPITCH + c * 4) = v;
            }
        }
        __syncthreads();

        // --- recurrent GEMM: 2 rows x 1 col x (r,z,n) per thread, packed f32x2 ---
        unsigned long long pr0 = 0, pz0 = 0, anh0 = 0, anx0 = 0;
        unsigned long long pr1 = 0, pz1 = 0, anh1 = 0, anx1 = 0;

        const float* hp0 = h_s + (ty * 2)     * HPITCH;
        const float* hp1 = h_s + (ty * 2 + 1) * HPITCH;
        const float* wr  = w_s + (0 * 16 + tx) * HPITCH;
        const float* wz  = w_s + (1 * 16 + tx) * HPITCH;
        const float* wn  = w_s + (2 * 16 + tx) * HPITCH;
        #pragma unroll 8
        for (int k4 = 0; k4 < HID / 4; k4++) {
            ulonglong2 h0v = *(const ulonglong2*)(hp0 + k4 * 4);
            ulonglong2 h1v = *(const ulonglong2*)(hp1 + k4 * 4);
            ulonglong2 wrv = *(const ulonglong2*)(wr  + k4 * 4);
            ulonglong2 wzv = *(const ulonglong2*)(wz  + k4 * 4);
            ulonglong2 wnv = *(const ulonglong2*)(wn  + k4 * 4);
            fma2(pr0,  h0v.x, wrv.x); fma2(pr0,  h0v.y, wrv.y);
            fma2(pz0,  h0v.x, wzv.x); fma2(pz0,  h0v.y, wzv.y);
            fma2(anh0, h0v.x, wnv.x); fma2(anh0, h0v.y, wnv.y);
            fma2(pr1,  h1v.x, wrv.x); fma2(pr1,  h1v.y, wrv.y);
            fma2(pz1,  h1v.x, wzv.x); fma2(pz1,  h1v.y, wzv.y);
            fma2(anh1, h1v.x, wnv.x); fma2(anh1, h1v.y, wnv.y);
        }
        // x-side projection (accumulates into r,z; n gets its own x accumulator)
        const float* xp0 = x_s  + (ty * 2)     * XPITCH;
        const float* xp1 = x_s  + (ty * 2 + 1) * XPITCH;
        const float* xr  = wx_s + (0 * 16 + tx) * XPITCH;
        const float* xz  = wx_s + (1 * 16 + tx) * XPITCH;
        const float* xn  = wx_s + (2 * 16 + tx) * XPITCH;
        #pragma unroll
        for (int k4 = 0; k4 < IN_DIM / 4; k4++) {
            ulonglong2 x0v = *(const ulonglong2*)(xp0 + k4 * 4);
            ulonglong2 x1v = *(const ulonglong2*)(xp1 + k4 * 4);
            ulonglong2 wrv = *(const ulonglong2*)(xr  + k4 * 4);
            ulonglong2 wzv = *(const ulonglong2*)(xz  + k4 * 4);
            ulonglong2 wnv = *(const ulonglong2*)(xn  + k4 * 4);
            fma2(pr0,  x0v.x, wrv.x); fma2(pr0,  x0v.y, wrv.y);
            fma2(pz0,  x0v.x, wzv.x); fma2(pz0,  x0v.y, wzv.y);
            fma2(anx0, x0v.x, wnv.x); fma2(anx0, x0v.y, wnv.y);
            fma2(pr1,  x1v.x, wrv.x); fma2(pr1,  x1v.y, wrv.y);
            fma2(pz1,  x1v.x, wzv.x); fma2(pz1,  x1v.y, wzv.y);
            fma2(anx1, x1v.x, wnv.x); fma2(anx1, x1v.y, wnv.y);
        }

        // --- gates + state update for the thread's 2 rows ---
        #pragma unroll
        for (int i2 = 0; i2 < 2; i2++) {
            int r = ty * 2 + i2;
            int b = rbase + r;
            float pre_r = redpair(i2 ? pr1  : pr0)  + bsum_r;
            float pre_z = redpair(i2 ? pz1  : pz0)  + bsum_z;
            float hn    = redpair(i2 ? anh1 : anh0) + bh_n;
            float xnv   = redpair(i2 ? anx1 : anx0) + bx_n;
            float rg = 1.f / (1.f + __expf(-pre_r));
            float zg = 1.f / (1.f + __expf(-pre_z));
            float ng = tanhf(xnv + rg * hn);
            float hold = h_s[r * HPITCH + jg];
            float hnew = (1.f - zg) * ng + zg * hold;
            hnxt[b * HID + jg] = hnew;
            g_hs[((size_t)s * BATCH + b) * HID + jg] = hnew;
        }
        grid_barrier();
    }
}

// =====================================================================
// Output GEMM: out[b][t][o] = hs[t][b][:] . W_out[o][:] + b_out[o]
// Tile: 64 rows (t*B+b) x 64 o, K=256 in 4 chunks
// =====================================================================
__global__ void __launch_bounds__(256) k_out(
    const float* __restrict__ W_out,   // [I][H]
    const float* __restrict__ b_out,   // [I]
    float* __restrict__ out)           // [B][T][I]
{
    __shared__ float hs_s[64 * XPITCH];
    __shared__ float ws_s[64 * XPITCH];
    const int tid = threadIdx.x;
    const int tx = tid & 15, ty = tid >> 4;
    const size_t mbase = (size_t)blockIdx.x * 64;

    unsigned long long acc[4][4];
    #pragma unroll
    for (int ii = 0; ii < 4; ii++)
        #pragma unroll
        for (int jj = 0; jj < 4; jj++) acc[ii][jj] = 0ULL;

    for (int kc = 0; kc < 4; kc++) {
        const int kofs = kc * 64;
        for (int i = tid; i < 1024; i += 256) {
            int row = i >> 4, c = i & 15;
            float4 v = *(const float4*)(g_hs + (mbase + row) * HID + kofs + c * 4);
            *(float4*)(hs_s + row * XPITCH + c * 4) = v;
        }
        for (int i = tid; i < 1024; i += 256) {
            int row = i >> 4, c = i & 15;
            float4 v = *(const float4*)(W_out + (size_t)row * HID + kofs + c * 4);
            *(float4*)(ws_s + row * XPITCH + c * 4) = v;
        }
        __syncthreads();
        #pragma unroll
        for (int k4 = 0; k4 < 16; k4++) {
            ulonglong2 a[4], w[4];
            #pragma unroll
            for (int ii = 0; ii < 4; ii++)
                a[ii] = *(const ulonglong2*)(hs_s + (ty * 4 + ii) * XPITCH + k4 * 4);
            #pragma unroll
            for (int jj = 0; jj < 4; jj++)
                w[jj] = *(const ulonglong2*)(ws_s + (jj * 16 + tx) * XPITCH + k4 * 4);
            #pragma unroll
            for (int ii = 0; ii < 4; ii++)
                #pragma unroll
                for (int jj = 0; jj < 4; jj++) {
                    fma2(acc[ii][jj], a[ii].x, w[jj].x);
                    fma2(acc[ii][jj], a[ii].y, w[jj].y);
                }
        }
        __syncthreads();
    }

    #pragma unroll
    for (int ii = 0; ii < 4; ii++) {
        size_t m = mbase + ty * 4 + ii;
        size_t t = m >> 8;          // m = t*B + b, B=256
        size_t b = m & 255;
        float* op = out + (b * T_STEPS + t) * IN_DIM;
        #pragma unroll
        for (int jj = 0; jj < 4; jj++) {
            int o = jj * 16 + tx;
            op[o] = redpair(acc[ii][jj]) + b_out[o];
        }
    }
}

extern "C" void kernel_launch(void* const* d_in, const int* in_sizes, int n_in,
                              void* d_out, int out_size)
{
    const float* input  = (const float*)d_in[0];
    const float* hidden = (const float*)d_in[1];
    const float* W_dec  = (const float*)d_in[2];
    const float* b_dec  = (const float*)d_in[3];
    const float* W_ih   = (const float*)d_in[4];
    const float* W_hh   = (const float*)d_in[5];
    const float* b_ih   = (const float*)d_in[6];
    const float* b_hh   = (const float*)d_in[7];
    const float* W_out  = (const float*)d_in[8];
    const float* b_out  = (const float*)d_in[9];
    float* out = (float*)d_out;

    cudaFuncSetAttribute(k_rec, cudaFuncAttributeMaxDynamicSharedMemorySize, SMEM_REC_BYTES);

    k_rec<<<REC_CTAS, 256, SMEM_REC_BYTES>>>(input, hidden, W_dec, b_dec,
                                             W_ih, W_hh, b_ih, b_hh);
    k_out<<<(T_STEPS * BATCH) / 64, 256>>>(W_out, b_out, out);
}

// round 3
// speedup vs baseline: 1.4506x; 1.4506x over previous
#include <cuda_runtime.h>

// Problem constants
#define T_STEPS 2048
#define BATCH   256
#define IN_DIM  64
#define HID     256

// Tiling: 16 row-groups x 8 j-CTAs = 128 CTAs.
// Each CTA: 16 batch rows x 32 hidden columns (x3 gates), K=256 split over 8 kslices.
#define GROUPS   16
#define JCTAS    8
#define ROWS     16      // rows per group
#define JW       32      // j columns per CTA

// Device scratch
__device__ float g_hs[(size_t)T_STEPS * BATCH * HID];   // h trajectory [T][B][H]
__device__ float g_h[2][BATCH * HID];                   // double-buffered state
__device__ unsigned int g_arr[GROUPS * 32];             // per-group monotonic arrival counters (padded)

typedef unsigned long long ull;

// ---- packed fp32x2 helpers ----
__device__ __forceinline__ void fma2(ull& acc, ull a, ull b) {
    asm("fma.rn.f32x2 %0, %1, %2, %0;" : "+l"(acc) : "l"(a), "l"(b));
}
__device__ __forceinline__ float redpair(ull v) {
    float lo = __uint_as_float((unsigned int)(v & 0xffffffffULL));
    float hi = __uint_as_float((unsigned int)(v >> 32));
    return lo + hi;
}
__device__ __forceinline__ ull packf(float lo, float hi) {
    return (ull)__float_as_uint(lo) | ((ull)__float_as_uint(hi) << 32);
}
__device__ __forceinline__ float fast_sig(float x) {
    return __fdividef(1.f, 1.f + __expf(-x));
}
__device__ __forceinline__ float fast_tanh(float x) {
    float y;
    asm("tanh.approx.f32 %0, %1;" : "=f"(y) : "f"(x));
    return y;
}
__device__ __forceinline__ unsigned int ld_acq(const unsigned int* p) {
    unsigned int v;
    asm volatile("ld.acquire.gpu.global.u32 %0, [%1];" : "=r"(v) : "l"(p));
    return v;
}

// =====================================================================
// Persistent recurrent kernel: register-resident weights
// =====================================================================
__global__ void __launch_bounds__(256, 1) k_rec(
    const float* __restrict__ input,   // [T][B][I]
    const float* __restrict__ hidden,  // [1][B][3]
    const float* __restrict__ W_dec,   // [H][3]
    const float* __restrict__ b_dec,   // [H]
    const float* __restrict__ W_ih,    // [3H][I]
    const float* __restrict__ W_hh,    // [3H][H]
    const float* __restrict__ b_ih,    // [3H]
    const float* __restrict__ b_hh)    // [3H]
{
    __shared__ float h_s[ROWS * HID];      // 16 KB, XOR-swizzled per row (64 chunks of 4 floats)
    __shared__ float x_s[ROWS * IN_DIM];   // 4 KB, linear

    const int tid = threadIdx.x;
    const int lane = tid & 31;
    const int warp = tid >> 5;
    const int kslice = lane & 7;          // owns k in [kslice*32, kslice*32+32)
    const int jw = lane >> 3;             // j within warp (0..3)
    const int jloc = warp * 4 + jw;       // 0..31
    const int grp = blockIdx.x >> 3;      // row group
    const int jc = blockIdx.x & 7;
    const int rbase = grp * ROWS;
    const int jbase = jc * JW;
    const int jg = jbase + jloc;          // global hidden column

    unsigned int* my_arr = &g_arr[grp * 32];

    // swizzled offset of column jg within an h_s row
    const int jsw = (((jg >> 2) ^ ((jg >> 5) & 7)) << 2) + (jg & 3);

    // --- load weights into registers (packed f32x2) ---
    ull whr[16], whz[16], whn[16];
    ull wxr[4],  wxz[4],  wxn[4];
    {
        const float4* W4 = (const float4*)W_hh;   // row stride 64 float4
        #pragma unroll
        for (int c = 0; c < 8; c++) {
            float4 vr = __ldg(&W4[((size_t)(0 * HID + jg)) * 64 + kslice * 8 + c]);
            float4 vz = __ldg(&W4[((size_t)(1 * HID + jg)) * 64 + kslice * 8 + c]);
            float4 vn = __ldg(&W4[((size_t)(2 * HID + jg)) * 64 + kslice * 8 + c]);
            whr[2*c] = packf(vr.x, vr.y); whr[2*c+1] = packf(vr.z, vr.w);
            whz[2*c] = packf(vz.x, vz.y); whz[2*c+1] = packf(vz.z, vz.w);
            whn[2*c] = packf(vn.x, vn.y); whn[2*c+1] = packf(vn.z, vn.w);
        }
        const float4* X4 = (const float4*)W_ih;   // row stride 16 float4
        #pragma unroll
        for (int c = 0; c < 2; c++) {
            float4 vr = __ldg(&X4[((size_t)(0 * HID + jg)) * 16 + kslice * 2 + c]);
            float4 vz = __ldg(&X4[((size_t)(1 * HID + jg)) * 16 + kslice * 2 + c]);
            float4 vn = __ldg(&X4[((size_t)(2 * HID + jg)) * 16 + kslice * 2 + c]);
            wxr[2*c] = packf(vr.x, vr.y); wxr[2*c+1] = packf(vr.z, vr.w);
            wxz[2*c] = packf(vz.x, vz.y); wxz[2*c+1] = packf(vz.z, vz.w);
            wxn[2*c] = packf(vn.x, vn.y); wxn[2*c+1] = packf(vn.z, vn.w);
        }
    }

    const float bsum_r = b_ih[jg]           + b_hh[jg];
    const float bsum_z = b_ih[HID + jg]     + b_hh[HID + jg];
    const float bx_n   = b_ih[2 * HID + jg];
    const float bh_n   = b_hh[2 * HID + jg];

    // --- h0: block b writes rows [2b, 2b+2) == its own group's rows ---
    {
        int base = blockIdx.x * 512;
        for (int u = tid; u < 512; u += 256) {
            int idx = base + u;
            int b = idx >> 8;
            int j = idx & 255;
            g_h[0][idx] = b_dec[j]
                        + hidden[b * 3 + 0] * W_dec[j * 3 + 0]
                        + hidden[b * 3 + 1] * W_dec[j * 3 + 1]
                        + hidden[b * 3 + 2] * W_dec[j * 3 + 2];
        }
    }
    __threadfence();
    __syncthreads();
    if (tid == 0) atomicAdd(my_arr, 1u);

    const int r0 = kslice, r1 = kslice + 8;

    // ---------------- time-step loop ----------------
    for (int s = 0; s < T_STEPS; s++) {
        // wait for all 8 group CTAs to have produced h for this step
        if (tid == 0) {
            unsigned int target = 8u * (unsigned int)(s + 1);
            while (ld_acq(my_arr) < target) { }
        }
        __syncthreads();

        // stage h tile [16][256] from g_h[s&1], XOR-swizzled, L1-bypass
        {
            const float4* hsrc = (const float4*)(g_h[s & 1] + (size_t)rbase * HID);
            #pragma unroll
            for (int it = 0; it < 4; it++) {
                int idx = tid + it * 256;            // 0..1023
                float4 v = __ldcg(hsrc + idx);
                int row = idx >> 6, c4 = idx & 63;
                int phys = c4 ^ ((c4 >> 3) & 7);
                *(float4*)(h_s + row * HID + phys * 4) = v;
            }
        }
        // stage x tile [16][64] (xs[0]=0, xs[s]=input[s-1])
        if (s == 0) {
            *(float4*)(x_s + tid * 4) = make_float4(0.f, 0.f, 0.f, 0.f);
        } else {
            const float4* xsrc = (const float4*)(input + ((size_t)(s - 1) * BATCH + rbase) * IN_DIM);
            *(float4*)(x_s + tid * 4) = xsrc[tid];
        }
        __syncthreads();

        float s0r, s0z, s0h, s0x, s1r, s1z, s1h, s1x;

        // rows processed in pairs (shfl latency overlap)
        #pragma unroll 1
        for (int rp = 0; rp < 8; rp++) {
            const float* hra = h_s + (2 * rp)     * HID;
            const float* hrb = h_s + (2 * rp + 1) * HID;
            const float* xra = x_s + (2 * rp)     * IN_DIM;
            const float* xrb = x_s + (2 * rp + 1) * IN_DIM;
            ull pra = 0, pza = 0, nha = 0, nxa = 0;
            ull prb = 0, pzb = 0, nhb = 0, nxb = 0;
            #pragma unroll
            for (int c = 0; c < 8; c++) {
                int p = (kslice << 3) + (c ^ kslice);
                ulonglong2 ha = *(const ulonglong2*)(hra + p * 4);
                ulonglong2 hb = *(const ulonglong2*)(hrb + p * 4);
                fma2(pra, ha.x, whr[2*c]); fma2(pra, ha.y, whr[2*c+1]);
                fma2(pza, ha.x, whz[2*c]); fma2(pza, ha.y, whz[2*c+1]);
                fma2(nha, ha.x, whn[2*c]); fma2(nha, ha.y, whn[2*c+1]);
                fma2(prb, hb.x, whr[2*c]); fma2(prb, hb.y, whr[2*c+1]);
                fma2(pzb, hb.x, whz[2*c]); fma2(pzb, hb.y, whz[2*c+1]);
                fma2(nhb, hb.x, whn[2*c]); fma2(nhb, hb.y, whn[2*c+1]);
            }
            #pragma unroll
            for (int c = 0; c < 2; c++) {
                ulonglong2 xa = *(const ulonglong2*)(xra + (kslice * 2 + c) * 4);
                ulonglong2 xb = *(const ulonglong2*)(xrb + (kslice * 2 + c) * 4);
                fma2(pra, xa.x, wxr[2*c]); fma2(pra, xa.y, wxr[2*c+1]);
                fma2(pza, xa.x, wxz[2*c]); fma2(pza, xa.y, wxz[2*c+1]);
                fma2(nxa, xa.x, wxn[2*c]); fma2(nxa, xa.y, wxn[2*c+1]);
                fma2(prb, xb.x, wxr[2*c]); fma2(prb, xb.y, wxr[2*c+1]);
                fma2(pzb, xb.x, wxz[2*c]); fma2(pzb, xb.y, wxz[2*c+1]);
                fma2(nxb, xb.x, wxn[2*c]); fma2(nxb, xb.y, wxn[2*c+1]);
            }
            float var = redpair(pra), vaz = redpair(pza), vah = redpair(nha), vax = redpair(nxa);
            float vbr = redpair(prb), vbz = redpair(pzb), vbh = redpair(nhb), vbx = redpair(nxb);
            #pragma unroll
            for (int m = 1; m <= 4; m <<= 1) {
                var += __shfl_xor_sync(0xffffffffu, var, m);
                vaz += __shfl_xor_sync(0xffffffffu, vaz, m);
                vah += __shfl_xor_sync(0xffffffffu, vah, m);
                vax += __shfl_xor_sync(0xffffffffu, vax, m);
                vbr += __shfl_xor_sync(0xffffffffu, vbr, m);
                vbz += __shfl_xor_sync(0xffffffffu, vbz, m);
                vbh += __shfl_xor_sync(0xffffffffu, vbh, m);
                vbx += __shfl_xor_sync(0xffffffffu, vbx, m);
            }
            int ra = 2 * rp, rb = 2 * rp + 1;
            if (ra == r0) { s0r = var; s0z = vaz; s0h = vah; s0x = vax; }
            if (rb == r0) { s0r = vbr; s0z = vbz; s0h = vbh; s0x = vbx; }
            if (ra == r1) { s1r = var; s1z = vaz; s1h = vah; s1x = vax; }
            if (rb == r1) { s1r = vbr; s1z = vbz; s1h = vbh; s1x = vbx; }
        }

        // --- gate math + state update: this thread owns rows r0, r1 at column jg ---
        float* hnxt = g_h[(s & 1) ^ 1];
        {
            float hold = h_s[r0 * HID + jsw];
            float rg = fast_sig(s0r + bsum_r);
            float zg = fast_sig(s0z + bsum_z);
            float ng = fast_tanh(s0x + bx_n + rg * (s0h + bh_n));
            float hnew = zg * (hold - ng) + ng;
            hnxt[(rbase + r0) * HID + jg] = hnew;
            g_hs[((size_t)s * BATCH + rbase + r0) * HID + jg] = hnew;
        }
        {
            float hold = h_s[r1 * HID + jsw];
            float rg = fast_sig(s1r + bsum_r);
            float zg = fast_sig(s1z + bsum_z);
            float ng = fast_tanh(s1x + bx_n + rg * (s1h + bh_n));
            float hnew = zg * (hold - ng) + ng;
            hnxt[(rbase + r1) * HID + jg] = hnew;
            g_hs[((size_t)s * BATCH + rbase + r1) * HID + jg] = hnew;
        }

        __threadfence();
        __syncthreads();
        if (tid == 0) atomicAdd(my_arr, 1u);
    }

    // reset counter for next graph replay (one CTA per group)
    if (jc == 0 && tid == 0) {
        unsigned int fin = 8u * (unsigned int)(T_STEPS + 1);
        while (ld_acq(my_arr) < fin) { }
        *my_arr = 0u;
        __threadfence();
    }
}

// =====================================================================
// Output GEMM: out[b][t][o] = hs[t][b][:] . W_out[o][:] + b_out[o]
// =====================================================================
#define XPITCH 68
__global__ void __launch_bounds__(256) k_out(
    const float* __restrict__ W_out,   // [I][H]
    const float* __restrict__ b_out,   // [I]
    float* __restrict__ out)           // [B][T][I]
{
    __shared__ float hs_s[64 * XPITCH];
    __shared__ float ws_s[64 * XPITCH];
    const int tid = threadIdx.x;
    const int tx = tid & 15, ty = tid >> 4;
    const size_t mbase = (size_t)blockIdx.x * 64;

    ull acc[4][4];
    #pragma unroll
    for (int ii = 0; ii < 4; ii++)
        #pragma unroll
        for (int jj = 0; jj < 4; jj++) acc[ii][jj] = 0ULL;

    for (int kc = 0; kc < 4; kc++) {
        const int kofs = kc * 64;
        for (int i = tid; i < 1024; i += 256) {
            int row = i >> 4, c = i & 15;
            float4 v = *(const float4*)(g_hs + (mbase + row) * HID + kofs + c * 4);
            *(float4*)(hs_s + row * XPITCH + c * 4) = v;
        }
        for (int i = tid; i < 1024; i += 256) {
            int row = i >> 4, c = i & 15;
            float4 v = *(const float4*)(W_out + (size_t)row * HID + kofs + c * 4);
            *(float4*)(ws_s + row * XPITCH + c * 4) = v;
        }
        __syncthreads();
        #pragma unroll
        for (int k4 = 0; k4 < 16; k4++) {
            ulonglong2 a[4], w[4];
            #pragma unroll
            for (int ii = 0; ii < 4; ii++)
                a[ii] = *(const ulonglong2*)(hs_s + (ty * 4 + ii) * XPITCH + k4 * 4);
            #pragma unroll
            for (int jj = 0; jj < 4; jj++)
                w[jj] = *(const ulonglong2*)(ws_s + (jj * 16 + tx) * XPITCH + k4 * 4);
            #pragma unroll
            for (int ii = 0; ii < 4; ii++)
                #pragma unroll
                for (int jj = 0; jj < 4; jj++) {
                    fma2(acc[ii][jj], a[ii].x, w[jj].x);
                    fma2(acc[ii][jj], a[ii].y, w[jj].y);
                }
        }
        __syncthreads();
    }

    #pragma unroll
    for (int ii = 0; ii < 4; ii++) {
        size_t m = mbase + ty * 4 + ii;
        size_t t = m >> 8;
        size_t b = m & 255;
        float* op = out + (b * T_STEPS + t) * IN_DIM;
        #pragma unroll
        for (int jj = 0; jj < 4; jj++) {
            int o = jj * 16 + tx;
            op[o] = redpair(acc[ii][jj]) + b_out[o];
        }
    }
}

extern "C" void kernel_launch(void* const* d_in, const int* in_sizes, int n_in,
                              void* d_out, int out_size)
{
    const float* input  = (const float*)d_in[0];
    const float* hidden = (const float*)d_in[1];
    const float* W_dec  = (const float*)d_in[2];
    const float* b_dec  = (const float*)d_in[3];
    const float* W_ih   = (const float*)d_in[4];
    const float* W_hh   = (const float*)d_in[5];
    const float* b_ih   = (const float*)d_in[6];
    const float* b_hh   = (const float*)d_in[7];
    const float* W_out  = (const float*)d_in[8];
    const float* b_out  = (const float*)d_in[9];
    float* out = (float*)d_out;

    k_rec<<<GROUPS * JCTAS, 256>>>(input, hidden, W_dec, b_dec,
                                   W_ih, W_hh, b_ih, b_hh);
    k_out<<<(T_STEPS * BATCH) / 64, 256>>>(W_out, b_out, out);
}